// round 1
// baseline (speedup 1.0000x reference)
#include <cuda_runtime.h>
#include <math_constants.h>
#include <stdint.h>

#define NROWS 8192      // B*M
#define VSZ   5003
#define NB    64
#define SSEQ  200
#define DDIM  128
#define NNEG  4
#define MAXA  8
#define INV_TAU (1.0f/0.07f)

// deterministic scratch (no atomics)
__device__ float g_fl[NROWS];
__device__ float g_cnt[NROWS];
__device__ float g_pm[NB][NNEG][MAXA];   // partial online-softmax max
__device__ float g_psum[NB][NNEG][MAXA]; // partial online-softmax sum
__device__ float g_possim[NB][MAXA];
__device__ int   g_na[NB];

// ---------------- focal: one block per row ----------------
__global__ __launch_bounds__(256) void focal_kernel(
    const float* __restrict__ logits,
    const int*   __restrict__ targets,
    const int*   __restrict__ mask)
{
    int r = blockIdx.x;
    int tid = threadIdx.x;
    int t = targets[r];
    bool valid = (t != -100) && (mask[r] == 1);
    if (!valid) {
        if (tid == 0) { g_fl[r] = 0.f; g_cnt[r] = 0.f; }
        return;
    }
    const float* row = logits + (size_t)r * VSZ;
    // peel to 16B alignment for float4 loads (row stride 5003 is odd)
    int mis = (int)(((uintptr_t)row >> 2) & 3);
    int pre = (4 - mis) & 3;
    const float4* rv = (const float4*)(row + pre);
    int nv = (VSZ - pre) >> 2;
    int tailstart = pre + (nv << 2);

    __shared__ float sred[8];

    // pass 1: row max
    float m = -CUDART_INF_F;
    if (tid < pre) m = row[tid];
    for (int i = tid; i < nv; i += 256) {
        float4 x = rv[i];
        m = fmaxf(m, fmaxf(fmaxf(x.x, x.y), fmaxf(x.z, x.w)));
    }
    for (int i = tailstart + tid; i < VSZ; i += 256) m = fmaxf(m, row[i]);
    #pragma unroll
    for (int o = 16; o; o >>= 1) m = fmaxf(m, __shfl_xor_sync(0xffffffffu, m, o));
    if ((tid & 31) == 0) sred[tid >> 5] = m;
    __syncthreads();
    if (tid == 0) {
        float mm = sred[0];
        #pragma unroll
        for (int i = 1; i < 8; i++) mm = fmaxf(mm, sred[i]);
        sred[0] = mm;
    }
    __syncthreads();
    m = sred[0];
    __syncthreads();   // protect sred before reuse

    // pass 2: sum exp (served mostly from L1)
    float s = 0.f;
    if (tid < pre) s = __expf(row[tid] - m);
    for (int i = tid; i < nv; i += 256) {
        float4 x = rv[i];
        s += __expf(x.x - m) + __expf(x.y - m) + __expf(x.z - m) + __expf(x.w - m);
    }
    for (int i = tailstart + tid; i < VSZ; i += 256) s += __expf(row[i] - m);
    #pragma unroll
    for (int o = 16; o; o >>= 1) s += __shfl_xor_sync(0xffffffffu, s, o);
    if ((tid & 31) == 0) sred[tid >> 5] = s;
    __syncthreads();
    if (tid == 0) {
        float ss = 0.f;
        #pragma unroll
        for (int i = 0; i < 8; i++) ss += sred[i];
        float lp = row[t] - m - logf(ss);   // log p_t
        float pt = __expf(lp);
        float om = 1.f - pt;
        g_fl[r]  = om * om * (-lp);
        g_cnt[r] = 1.f;
    }
}

// ---------------- contrastive: grid (4 neighbors, 64 batches), warp = anchor ----------------
__global__ __launch_bounds__(256) void contrast_kernel(
    const float* __restrict__ emb,
    const int*   __restrict__ pids,
    const int*   __restrict__ amask)
{
    int b = blockIdx.y;
    int j = blockIdx.x;                 // which of the 4 neighbor batches
    int nb = j + (j >= b ? 1 : 0);      // others[b][j] = first 4 of range(B)\{b}
    int tid = threadIdx.x, lane = tid & 31, w = tid >> 5;

    __shared__ unsigned char s_nv[SSEQ];  // neighbor validity
    __shared__ unsigned char s_ov[SSEQ];  // own validity
    __shared__ int s_aidx[MAXA], s_pidx[MAXA];
    __shared__ int s_na;

    if (tid < SSEQ) {
        s_nv[tid] = (amask[nb * SSEQ + tid] == 1 && pids[nb * SSEQ + tid] > 0) ? 1 : 0;
        s_ov[tid] = (amask[b  * SSEQ + tid] == 1 && pids[b  * SSEQ + tid] > 0) ? 1 : 0;
    }
    __syncthreads();
    if (tid == 0) {
        int first16[16];
        #pragma unroll
        for (int i = 0; i < 16; i++) first16[i] = 0;
        int n = 0;
        for (int s = 0; s < SSEQ; s++) if (s_ov[s]) { if (n < 16) first16[n] = s; n++; }
        int na = n / 2; if (na > MAXA) na = MAXA;
        s_na = na;
        #pragma unroll
        for (int i = 0; i < MAXA; i++) {
            s_aidx[i] = first16[i];
            int pi = na + i;
            s_pidx[i] = (pi < 16) ? first16[pi] : 0;
        }
        if (j == 0) g_na[b] = na;
    }
    __syncthreads();
    int na = s_na;

    if (w < na) {
        // anchor: lane holds dims [4*lane .. 4*lane+3]
        float4 a = ((const float4*)(emb + ((size_t)b * SSEQ + s_aidx[w]) * DDIM))[lane];
        float n2 = a.x * a.x + a.y * a.y + a.z * a.z + a.w * a.w;
        #pragma unroll
        for (int o = 16; o; o >>= 1) n2 += __shfl_xor_sync(0xffffffffu, n2, o);
        float inva = 1.0f / fmaxf(sqrtf(n2), 1e-12f);
        a.x *= inva; a.y *= inva; a.z *= inva; a.w *= inva;

        // positive
        float4 p = ((const float4*)(emb + ((size_t)b * SSEQ + s_pidx[w]) * DDIM))[lane];
        float pn2 = p.x * p.x + p.y * p.y + p.z * p.z + p.w * p.w;
        float pd  = a.x * p.x + a.y * p.y + a.z * p.z + a.w * p.w;
        #pragma unroll
        for (int o = 16; o; o >>= 1) {
            pn2 += __shfl_xor_sync(0xffffffffu, pn2, o);
            pd  += __shfl_xor_sync(0xffffffffu, pd,  o);
        }
        float possim = pd * (1.0f / fmaxf(sqrtf(pn2), 1e-12f)) * INV_TAU;
        if (j == 0 && lane == 0) g_possim[b][w] = possim;

        // negatives: 200 candidates from neighbor nb, online logsumexp partial
        float m = -CUDART_INF_F, ssum = 0.f;
        const float* nbbase = emb + (size_t)nb * SSEQ * DDIM;
        for (int s = 0; s < SSEQ; s++) {
            if (!s_nv[s]) continue;     // exact: masked entries contribute exp(-1e9-m)=0
            float4 g = ((const float4*)(nbbase + s * DDIM))[lane];
            float d  = a.x * g.x + a.y * g.y + a.z * g.z + a.w * g.w;
            float gn = g.x * g.x + g.y * g.y + g.z * g.z + g.w * g.w;
            #pragma unroll
            for (int o = 16; o; o >>= 1) {
                d  += __shfl_xor_sync(0xffffffffu, d,  o);
                gn += __shfl_xor_sync(0xffffffffu, gn, o);
            }
            float sim = d * (1.0f / fmaxf(sqrtf(gn), 1e-12f)) * INV_TAU;
            float nm = fmaxf(m, sim);
            ssum = ssum * __expf(m - nm) + __expf(sim - nm);
            m = nm;
        }
        if (lane == 0) { g_pm[b][j][w] = m; g_psum[b][j][w] = ssum; }
    }
}

// ---------------- finalize: single block, deterministic tree reduction ----------------
__global__ __launch_bounds__(256) void finalize_kernel(float* __restrict__ out)
{
    int tid = threadIdx.x;
    __shared__ float sred[8];

    float fs = 0.f, cnt = 0.f;
    for (int r = tid; r < NROWS; r += 256) { fs += g_fl[r]; cnt += g_cnt[r]; }

    float closs = 0.f;
    for (int idx = tid; idx < NB * MAXA; idx += 256) {
        int b = idx >> 3, aq = idx & 7;
        if (aq < g_na[b]) {
            float ps = g_possim[b][aq];
            float m = ps, ssum = 1.f;   // positive term
            #pragma unroll
            for (int jj = 0; jj < NNEG; jj++) {
                float pm  = g_pm[b][jj][aq];
                float pss = g_psum[b][jj][aq];
                if (pss > 0.f) {
                    float nm = fmaxf(m, pm);
                    ssum = ssum * __expf(m - nm) + pss * __expf(pm - nm);
                    m = nm;
                }
            }
            closs += (m + logf(ssum)) - ps;
        }
    }
    float pairs = (tid < NB) ? (float)g_na[tid] : 0.f;

    float vals[4] = { fs, cnt, closs, pairs };
    float res[4]  = { 0.f, 0.f, 0.f, 0.f };
    #pragma unroll
    for (int k = 0; k < 4; k++) {
        float v = vals[k];
        #pragma unroll
        for (int o = 16; o; o >>= 1) v += __shfl_xor_sync(0xffffffffu, v, o);
        __syncthreads();
        if ((tid & 31) == 0) sred[tid >> 5] = v;
        __syncthreads();
        if (tid == 0) {
            float t = 0.f;
            #pragma unroll
            for (int i = 0; i < 8; i++) t += sred[i];
            res[k] = t;
        }
    }
    if (tid == 0) {
        float focal = res[1] > 0.f ? res[0] / res[1] : 0.f;
        float contr = res[3] > 0.f ? res[2] / res[3] : 0.f;
        out[0] = 0.6f * focal + 0.2f * contr;
    }
}

extern "C" void kernel_launch(void* const* d_in, const int* in_sizes, int n_in,
                              void* d_out, int out_size)
{
    const float* logits  = (const float*)d_in[0];
    const int*   targets = (const int*)d_in[1];
    const int*   mask    = (const int*)d_in[2];
    const float* emb     = (const float*)d_in[3];
    const int*   pids    = (const int*)d_in[4];
    const int*   amask   = (const int*)d_in[5];
    float* out = (float*)d_out;

    focal_kernel<<<NROWS, 256>>>(logits, targets, mask);
    contrast_kernel<<<dim3(NNEG, NB), 256>>>(emb, pids, amask);
    finalize_kernel<<<1, 256>>>(out);
}

// round 2
// speedup vs baseline: 1.1698x; 1.1698x over previous
#include <cuda_runtime.h>
#include <math_constants.h>
#include <stdint.h>

#define NROWS 8192      // B*M
#define VSZ   5003
#define NB    64
#define SSEQ  200
#define DDIM  128
#define NNEG  4
#define MAXA  8
#define INV_TAU (1.0f/0.07f)

// deterministic scratch (no atomics anywhere)
__device__ float g_fl[NROWS];
__device__ float g_cnt[NROWS];
__device__ float g_nemb[NB * SSEQ * DDIM];       // normalized embeddings
__device__ unsigned char g_vld[NB * SSEQ];
__device__ int   g_aidx[NB][MAXA];
__device__ int   g_pidx[NB][MAXA];
__device__ int   g_na[NB];
__device__ float g_pm[NB][NNEG][MAXA];
__device__ float g_psum[NB][NNEG][MAXA];
__device__ float g_possim[NB][MAXA];

// ---------------- fused: focal (blocks 0..8191, one per row, single-pass
// online softmax) + prep (blocks 8192..8255, normalize + anchor select) -----
__global__ __launch_bounds__(256) void focal_prep_kernel(
    const float* __restrict__ logits,
    const int*   __restrict__ targets,
    const int*   __restrict__ mask,
    const float* __restrict__ emb,
    const int*   __restrict__ pids,
    const int*   __restrict__ amask)
{
    int tid = threadIdx.x;
    int lane = tid & 31, w = tid >> 5;

    if (blockIdx.x >= NROWS) {
        // ---------- prep for batch b ----------
        int b = blockIdx.x - NROWS;
        __shared__ unsigned char s_v[SSEQ];
        if (tid < SSEQ) {
            unsigned char v = (amask[b * SSEQ + tid] == 1 && pids[b * SSEQ + tid] > 0) ? 1 : 0;
            s_v[tid] = v;
            g_vld[b * SSEQ + tid] = v;
        }
        // normalize: warp w handles vectors s = w, w+8, ...
        for (int s = w; s < SSEQ; s += 8) {
            const float4* src = (const float4*)(emb + ((size_t)b * SSEQ + s) * DDIM);
            float4 x = src[lane];
            float n2 = x.x * x.x + x.y * x.y + x.z * x.z + x.w * x.w;
            #pragma unroll
            for (int o = 16; o; o >>= 1) n2 += __shfl_xor_sync(0xffffffffu, n2, o);
            float inv = 1.0f / fmaxf(sqrtf(n2), 1e-12f);
            x.x *= inv; x.y *= inv; x.z *= inv; x.w *= inv;
            ((float4*)(g_nemb + ((size_t)b * SSEQ + s) * DDIM))[lane] = x;
        }
        __syncthreads();
        if (tid == 0) {
            int first16[16];
            #pragma unroll
            for (int i = 0; i < 16; i++) first16[i] = 0;
            int n = 0;
            for (int s = 0; s < SSEQ; s++) if (s_v[s]) { if (n < 16) first16[n] = s; n++; }
            int na = n / 2; if (na > MAXA) na = MAXA;
            g_na[b] = na;
            #pragma unroll
            for (int i = 0; i < MAXA; i++) {
                g_aidx[b][i] = first16[i];
                int pi = na + i;
                g_pidx[b][i] = (pi < 16) ? first16[pi] : 0;
            }
        }
        return;
    }

    // ---------- focal: single-pass online softmax, one block per row ----------
    int r = blockIdx.x;
    int t = targets[r];
    bool valid = (t != -100) && (mask[r] == 1);
    if (!valid) {
        if (tid == 0) { g_fl[r] = 0.f; g_cnt[r] = 0.f; }
        return;
    }
    const float* row = logits + (size_t)r * VSZ;
    int pre = (4 - (int)(((uintptr_t)row >> 2) & 3)) & 3;   // peel to 16B align
    const float4* rv = (const float4*)(row + pre);
    int nvq = (VSZ - pre) >> 2;
    int tail = pre + (nvq << 2);

    float m = -CUDART_INF_F, s = 0.f;
    if (tid < pre) { m = row[tid]; s = 1.f; }
    for (int i = tid; i < nvq; i += 256) {
        float4 x = rv[i];
        float mx = fmaxf(fmaxf(x.x, x.y), fmaxf(x.z, x.w));
        if (mx > m) { s *= __expf(m - mx); m = mx; }   // rare (~7 times/thread)
        s += __expf(x.x - m) + __expf(x.y - m) + __expf(x.z - m) + __expf(x.w - m);
    }
    for (int i = tail + tid; i < VSZ; i += 256) {
        float x = row[i];
        if (x > m) { s *= __expf(m - x); m = x; }
        s += __expf(x - m);
    }
    // warp merge of (m, s)
    #pragma unroll
    for (int o = 16; o; o >>= 1) {
        float om = __shfl_xor_sync(0xffffffffu, m, o);
        float os = __shfl_xor_sync(0xffffffffu, s, o);
        float nm = fmaxf(m, om);
        if (nm > -CUDART_INF_F) {
            s = s * __expf(m - nm) + os * __expf(om - nm);
            m = nm;
        }
    }
    __shared__ float sm[8], ss[8];
    if (lane == 0) { sm[w] = m; ss[w] = s; }
    __syncthreads();
    if (tid == 0) {
        float M = sm[0], S = ss[0];
        #pragma unroll
        for (int i = 1; i < 8; i++) {
            float om = sm[i], os = ss[i];
            float nm = fmaxf(M, om);
            S = S * __expf(M - nm) + os * __expf(om - nm);
            M = nm;
        }
        float lp = row[t] - M - logf(S);   // log p_t
        float pt = __expf(lp);
        float omp = 1.f - pt;
        g_fl[r]  = omp * omp * (-lp);
        g_cnt[r] = 1.f;
    }
}

// ---------------- contrastive: grid (4 neighbors, 64 batches) -------------
// warp = anchor; LANE owns whole negatives (full 128-dim dot in registers,
// anchor broadcast from SMEM) -> no shuffles in the hot loop.
__global__ __launch_bounds__(256) void contrast_kernel()
{
    int b = blockIdx.y;
    int j = blockIdx.x;
    int nb = j + (j >= b ? 1 : 0);      // others[b][j]
    int tid = threadIdx.x, lane = tid & 31, w = tid >> 5;

    __shared__ float s_anch[MAXA][DDIM];
    // cooperative anchor fill: thread -> (anchor a = tid/32, float4 part = tid%32)
    {
        int a = tid >> 5, part = tid & 31;
        int ai = g_aidx[b][a];
        ((float4*)s_anch[a])[part] =
            ((const float4*)(g_nemb + ((size_t)b * SSEQ + ai) * DDIM))[part];
    }
    __syncthreads();

    int na = g_na[b];
    if (w < na) {
        const float4* av = (const float4*)s_anch[w];

        if (j == 0) {
            // positive similarity (normalized embeddings -> plain dot)
            int pi = g_pidx[b][w];
            float4 p = ((const float4*)(g_nemb + ((size_t)b * SSEQ + pi) * DDIM))[lane];
            float4 a4 = av[lane];
            float d = a4.x * p.x + a4.y * p.y + a4.z * p.z + a4.w * p.w;
            #pragma unroll
            for (int o = 16; o; o >>= 1) d += __shfl_xor_sync(0xffffffffu, d, o);
            if (lane == 0) g_possim[b][w] = d * INV_TAU;
        }

        // negatives: lane owns s = lane, lane+32, ...
        float m = -CUDART_INF_F, ssum = 0.f;
        const float* nbase = g_nemb + (size_t)nb * SSEQ * DDIM;
        const unsigned char* nvld = g_vld + nb * SSEQ;
        for (int s = lane; s < SSEQ; s += 32) {
            if (nvld[s]) {   // exact: masked entries contribute exp(-1e9-m)=0
                const float4* gv = (const float4*)(nbase + s * DDIM);
                float acc0 = 0.f, acc1 = 0.f, acc2 = 0.f, acc3 = 0.f;
                #pragma unroll
                for (int d = 0; d < 32; d += 4) {
                    float4 g0 = gv[d + 0], a0 = av[d + 0];
                    float4 g1 = gv[d + 1], a1 = av[d + 1];
                    float4 g2 = gv[d + 2], a2 = av[d + 2];
                    float4 g3 = gv[d + 3], a3 = av[d + 3];
                    acc0 += g0.x * a0.x + g0.y * a0.y + g0.z * a0.z + g0.w * a0.w;
                    acc1 += g1.x * a1.x + g1.y * a1.y + g1.z * a1.z + g1.w * a1.w;
                    acc2 += g2.x * a2.x + g2.y * a2.y + g2.z * a2.z + g2.w * a2.w;
                    acc3 += g3.x * a3.x + g3.y * a3.y + g3.z * a3.z + g3.w * a3.w;
                }
                float sim = ((acc0 + acc1) + (acc2 + acc3)) * INV_TAU;
                float nm = fmaxf(m, sim);
                ssum = ssum * __expf(m - nm) + __expf(sim - nm);
                m = nm;
            }
        }
        // one shfl online-merge across lanes (shuffles outside divergent region)
        #pragma unroll
        for (int o = 16; o; o >>= 1) {
            float om = __shfl_xor_sync(0xffffffffu, m, o);
            float os = __shfl_xor_sync(0xffffffffu, ssum, o);
            float nm = fmaxf(m, om);
            if (nm > -CUDART_INF_F) {
                ssum = ssum * __expf(m - nm) + os * __expf(om - nm);
                m = nm;
            }
        }
        if (lane == 0) { g_pm[b][j][w] = m; g_psum[b][j][w] = ssum; }
    }
}

// ---------------- finalize: single block, deterministic -------------------
__global__ __launch_bounds__(256) void finalize_kernel(float* __restrict__ out)
{
    int tid = threadIdx.x;
    __shared__ float sred[8];

    float fs = 0.f, cnt = 0.f;
    for (int r = tid; r < NROWS; r += 256) { fs += g_fl[r]; cnt += g_cnt[r]; }

    float closs = 0.f;
    for (int idx = tid; idx < NB * MAXA; idx += 256) {
        int b = idx >> 3, aq = idx & 7;
        if (aq < g_na[b]) {
            float ps = g_possim[b][aq];
            float m = ps, ssum = 1.f;   // positive term
            #pragma unroll
            for (int jj = 0; jj < NNEG; jj++) {
                float pm  = g_pm[b][jj][aq];
                float pss = g_psum[b][jj][aq];
                if (pss > 0.f) {
                    float nm = fmaxf(m, pm);
                    ssum = ssum * __expf(m - nm) + pss * __expf(pm - nm);
                    m = nm;
                }
            }
            closs += (m + logf(ssum)) - ps;
        }
    }
    float pairs = (tid < NB) ? (float)g_na[tid] : 0.f;

    float vals[4] = { fs, cnt, closs, pairs };
    float res[4]  = { 0.f, 0.f, 0.f, 0.f };
    #pragma unroll
    for (int k = 0; k < 4; k++) {
        float v = vals[k];
        #pragma unroll
        for (int o = 16; o; o >>= 1) v += __shfl_xor_sync(0xffffffffu, v, o);
        __syncthreads();
        if ((tid & 31) == 0) sred[tid >> 5] = v;
        __syncthreads();
        if (tid == 0) {
            float t = 0.f;
            #pragma unroll
            for (int i = 0; i < 8; i++) t += sred[i];
            res[k] = t;
        }
    }
    if (tid == 0) {
        float focal = res[1] > 0.f ? res[0] / res[1] : 0.f;
        float contr = res[3] > 0.f ? res[2] / res[3] : 0.f;
        out[0] = 0.6f * focal + 0.2f * contr;
    }
}

extern "C" void kernel_launch(void* const* d_in, const int* in_sizes, int n_in,
                              void* d_out, int out_size)
{
    const float* logits  = (const float*)d_in[0];
    const int*   targets = (const int*)d_in[1];
    const int*   mask    = (const int*)d_in[2];
    const float* emb     = (const float*)d_in[3];
    const int*   pids    = (const int*)d_in[4];
    const int*   amask   = (const int*)d_in[5];
    float* out = (float*)d_out;

    focal_prep_kernel<<<NROWS + NB, 256>>>(logits, targets, mask, emb, pids, amask);
    contrast_kernel<<<dim3(NNEG, NB), 256>>>();
    finalize_kernel<<<1, 256>>>(out);
}

// round 3
// speedup vs baseline: 1.6540x; 1.4139x over previous
#include <cuda_runtime.h>
#include <math_constants.h>
#include <stdint.h>

#define NROWS 8192      // B*M
#define VSZ   5003
#define NB    64
#define SSEQ  200
#define DDIM  128
#define NNEG  4
#define MAXA  8
#define INV_TAU (1.0f/0.07f)

// deterministic scratch (no atomics anywhere)
__device__ float g_fl[NROWS];
__device__ float g_cnt[NROWS];
__device__ float g_nemb[NB * SSEQ * DDIM];       // normalized embeddings
__device__ unsigned char g_vld[NB * SSEQ];
__device__ int   g_aidx[NB][MAXA];
__device__ int   g_pidx[NB][MAXA];
__device__ int   g_na[NB];
__device__ float g_pm[NB][NNEG][MAXA];
__device__ float g_psum[NB][NNEG][MAXA];
__device__ float g_possim[NB][MAXA];

// ---------------- prep: normalize embeddings + anchor/positive select -----
__global__ __launch_bounds__(256) void prep_kernel(
    const float* __restrict__ emb,
    const int*   __restrict__ pids,
    const int*   __restrict__ amask)
{
    int b = blockIdx.x;
    int tid = threadIdx.x, lane = tid & 31, w = tid >> 5;
    __shared__ unsigned char s_v[SSEQ];
    if (tid < SSEQ) {
        unsigned char v = (amask[b * SSEQ + tid] == 1 && pids[b * SSEQ + tid] > 0) ? 1 : 0;
        s_v[tid] = v;
        g_vld[b * SSEQ + tid] = v;
    }
    for (int s = w; s < SSEQ; s += 8) {
        const float4* src = (const float4*)(emb + ((size_t)b * SSEQ + s) * DDIM);
        float4 x = src[lane];
        float n2 = x.x * x.x + x.y * x.y + x.z * x.z + x.w * x.w;
        #pragma unroll
        for (int o = 16; o; o >>= 1) n2 += __shfl_xor_sync(0xffffffffu, n2, o);
        float inv = 1.0f / fmaxf(sqrtf(n2), 1e-12f);
        x.x *= inv; x.y *= inv; x.z *= inv; x.w *= inv;
        ((float4*)(g_nemb + ((size_t)b * SSEQ + s) * DDIM))[lane] = x;
    }
    __syncthreads();
    if (tid == 0) {
        int first16[16];
        #pragma unroll
        for (int i = 0; i < 16; i++) first16[i] = 0;
        int n = 0;
        for (int s = 0; s < SSEQ; s++) if (s_v[s]) { if (n < 16) first16[n] = s; n++; }
        int na = n / 2; if (na > MAXA) na = MAXA;
        g_na[b] = na;
        #pragma unroll
        for (int i = 0; i < MAXA; i++) {
            g_aidx[b][i] = first16[i];
            int pi = na + i;
            g_pidx[b][i] = (pi < 16) ? first16[pi] : 0;
        }
    }
}

// ---------------- contrastive: block = (b, j) ------------------------------
// warp w owns negatives s = w, w+8, ...; lane owns dims 4*lane..4*lane+3
// (coalesced). All 8 anchors register-blocked per lane.
__global__ __launch_bounds__(256) void contrast_kernel()
{
    int b = blockIdx.x >> 2, j = blockIdx.x & 3;
    int nb = j + (j >= b ? 1 : 0);      // others[b][j]
    int tid = threadIdx.x, lane = tid & 31, w = tid >> 5;

    __shared__ float s_anch[MAXA][DDIM];
    __shared__ float s_m[MAXA][MAXA], s_s[MAXA][MAXA];   // [warp][anchor]

    {   // cooperative anchor fill (all 8; aidx defaults to 0, safe)
        int ai = g_aidx[b][w];
        ((float4*)s_anch[w])[lane] =
            ((const float4*)(g_nemb + ((size_t)b * SSEQ + ai) * DDIM))[lane];
    }
    __syncthreads();
    int na = g_na[b];

    // positive similarity (only j==0 blocks): warp w -> anchor w
    if (j == 0 && w < na) {
        int pi = g_pidx[b][w];
        float4 p  = ((const float4*)(g_nemb + ((size_t)b * SSEQ + pi) * DDIM))[lane];
        float4 a4 = ((const float4*)s_anch[w])[lane];
        float d = a4.x * p.x + a4.y * p.y + a4.z * p.z + a4.w * p.w;
        #pragma unroll
        for (int o = 16; o; o >>= 1) d += __shfl_xor_sync(0xffffffffu, d, o);
        if (lane == 0) g_possim[b][w] = d * INV_TAU;
    }

    // register-block all anchors: A[a] = anchor a, dims 4*lane..+3
    float4 A[MAXA];
    #pragma unroll
    for (int a = 0; a < MAXA; a++) A[a] = ((const float4*)s_anch[a])[lane];

    float m[MAXA], sa[MAXA];
    #pragma unroll
    for (int a = 0; a < MAXA; a++) { m[a] = -CUDART_INF_F; sa[a] = 0.f; }

    const float* nbase = g_nemb + (size_t)nb * SSEQ * DDIM;
    const unsigned char* nvld = g_vld + nb * SSEQ;
    for (int s = w; s < SSEQ; s += 8) {          // warp-uniform predicate
        if (!nvld[s]) continue;
        float4 g = ((const float4*)(nbase + (size_t)s * DDIM))[lane];
        float acc[MAXA];
        #pragma unroll
        for (int a = 0; a < MAXA; a++)
            acc[a] = A[a].x * g.x + A[a].y * g.y + A[a].z * g.z + A[a].w * g.w;
        #pragma unroll
        for (int a = 0; a < MAXA; a++)
            #pragma unroll
            for (int o = 16; o; o >>= 1)
                acc[a] += __shfl_xor_sync(0xffffffffu, acc[a], o);
        #pragma unroll
        for (int a = 0; a < MAXA; a++) {
            float sim = acc[a] * INV_TAU;
            float nm = fmaxf(m[a], sim);
            sa[a] = sa[a] * __expf(m[a] - nm) + __expf(sim - nm);
            m[a] = nm;
        }
    }
    if (lane == 0) {
        #pragma unroll
        for (int a = 0; a < MAXA; a++) { s_m[w][a] = m[a]; s_s[w][a] = sa[a]; }
    }
    __syncthreads();
    // deterministic merge across the 8 warps: thread a handles anchor a
    if (tid < MAXA) {
        float M = -CUDART_INF_F, S = 0.f;
        #pragma unroll
        for (int ww = 0; ww < MAXA; ww++) {
            float pm = s_m[ww][tid], ps = s_s[ww][tid];
            if (ps > 0.f) {
                float nm = fmaxf(M, pm);
                S = S * __expf(M - nm) + ps * __expf(pm - nm);
                M = nm;
            }
        }
        g_pm[b][j][tid] = M; g_psum[b][j][tid] = S;
    }
}

// ---------------- focal: one block per row, two-pass, loads kept in regs ---
__global__ __launch_bounds__(256) void focal_kernel(
    const float* __restrict__ logits,
    const int*   __restrict__ targets,
    const int*   __restrict__ mask)
{
    int r = blockIdx.x;
    int tid = threadIdx.x, lane = tid & 31, w = tid >> 5;
    int t = targets[r];
    bool valid = (t != -100) && (mask[r] == 1);
    if (!valid) {
        if (tid == 0) { g_fl[r] = 0.f; g_cnt[r] = 0.f; }
        return;
    }
    const float* row = logits + (size_t)r * VSZ;
    int pre = (4 - (int)(((uintptr_t)row >> 2) & 3)) & 3;   // peel to 16B align
    const float4* rv = (const float4*)(row + pre);
    // nvq == 1250 for every peel value; covered = 5000
    int tail = pre + 5000;

    // ---- batched loads, kept in registers for both passes ----
    float4 x0 = rv[tid];
    float4 x1 = rv[tid + 256];
    float4 x2 = rv[tid + 512];
    float4 x3 = rv[tid + 768];
    bool has4 = (tid < 226);            // tid+1024 < 1250
    float4 x4 = has4 ? rv[tid + 1024] : make_float4(-CUDART_INF_F, -CUDART_INF_F, -CUDART_INF_F, -CUDART_INF_F);
    float e0 = -CUDART_INF_F, e1 = -CUDART_INF_F, e2 = -CUDART_INF_F;
    if (tid < pre) e0 = row[tid];
    {
        int i = tail + tid;
        if (i < VSZ) e1 = row[i];
        i += 256;
        if (i < VSZ) e2 = row[i];       // never taken (<=3 tail), keeps logic general
    }

    // ---- pass 1: block max ----
    float m0 = fmaxf(fmaxf(x0.x, x0.y), fmaxf(x0.z, x0.w));
    float m1 = fmaxf(fmaxf(x1.x, x1.y), fmaxf(x1.z, x1.w));
    float m2 = fmaxf(fmaxf(x2.x, x2.y), fmaxf(x2.z, x2.w));
    float m3 = fmaxf(fmaxf(x3.x, x3.y), fmaxf(x3.z, x3.w));
    float m4 = fmaxf(fmaxf(x4.x, x4.y), fmaxf(x4.z, x4.w));
    float m = fmaxf(fmaxf(fmaxf(m0, m1), fmaxf(m2, m3)), fmaxf(m4, fmaxf(e0, fmaxf(e1, e2))));
    #pragma unroll
    for (int o = 16; o; o >>= 1) m = fmaxf(m, __shfl_xor_sync(0xffffffffu, m, o));
    __shared__ float sm[8], ss[8];
    if (lane == 0) sm[w] = m;
    __syncthreads();
    if (tid == 0) {
        float M = sm[0];
        #pragma unroll
        for (int i = 1; i < 8; i++) M = fmaxf(M, sm[i]);
        sm[0] = M;
    }
    __syncthreads();
    m = sm[0];

    // ---- pass 2: sum of exps, pure register math ----
    float s0 = __expf(x0.x - m) + __expf(x0.y - m) + __expf(x0.z - m) + __expf(x0.w - m);
    float s1 = __expf(x1.x - m) + __expf(x1.y - m) + __expf(x1.z - m) + __expf(x1.w - m);
    float s2 = __expf(x2.x - m) + __expf(x2.y - m) + __expf(x2.z - m) + __expf(x2.w - m);
    float s3 = __expf(x3.x - m) + __expf(x3.y - m) + __expf(x3.z - m) + __expf(x3.w - m);
    float s4 = 0.f;
    if (has4) s4 = __expf(x4.x - m) + __expf(x4.y - m) + __expf(x4.z - m) + __expf(x4.w - m);
    float se = 0.f;
    if (e0 > -CUDART_INF_F) se += __expf(e0 - m);
    if (e1 > -CUDART_INF_F) se += __expf(e1 - m);
    if (e2 > -CUDART_INF_F) se += __expf(e2 - m);
    float s = ((s0 + s1) + (s2 + s3)) + (s4 + se);
    #pragma unroll
    for (int o = 16; o; o >>= 1) s += __shfl_xor_sync(0xffffffffu, s, o);
    if (lane == 0) ss[w] = s;
    __syncthreads();
    if (tid == 0) {
        float S = 0.f;
        #pragma unroll
        for (int i = 0; i < 8; i++) S += ss[i];
        float lp = row[t] - m - logf(S);   // log p_t
        float pt = __expf(lp);
        float omp = 1.f - pt;
        g_fl[r]  = omp * omp * (-lp);
        g_cnt[r] = 1.f;
    }
}

// ---------------- finalize: single block, deterministic -------------------
__global__ __launch_bounds__(256) void finalize_kernel(float* __restrict__ out)
{
    int tid = threadIdx.x;
    __shared__ float sred[8];

    float fs = 0.f, cnt = 0.f;
    const float4* fv = (const float4*)g_fl;
    const float4* cv = (const float4*)g_cnt;
    for (int q = tid; q < NROWS / 4; q += 256) {
        float4 f = fv[q], c = cv[q];
        fs  += (f.x + f.y) + (f.z + f.w);
        cnt += (c.x + c.y) + (c.z + c.w);
    }

    float closs = 0.f;
    for (int idx = tid; idx < NB * MAXA; idx += 256) {
        int b = idx >> 3, aq = idx & 7;
        if (aq < g_na[b]) {
            float ps = g_possim[b][aq];
            float m = ps, ssum = 1.f;   // positive term
            #pragma unroll
            for (int jj = 0; jj < NNEG; jj++) {
                float pm  = g_pm[b][jj][aq];
                float pss = g_psum[b][jj][aq];
                if (pss > 0.f) {
                    float nm = fmaxf(m, pm);
                    ssum = ssum * __expf(m - nm) + pss * __expf(pm - nm);
                    m = nm;
                }
            }
            closs += (m + logf(ssum)) - ps;
        }
    }
    float pairs = (tid < NB) ? (float)g_na[tid] : 0.f;

    float vals[4] = { fs, cnt, closs, pairs };
    float res[4]  = { 0.f, 0.f, 0.f, 0.f };
    #pragma unroll
    for (int k = 0; k < 4; k++) {
        float v = vals[k];
        #pragma unroll
        for (int o = 16; o; o >>= 1) v += __shfl_xor_sync(0xffffffffu, v, o);
        __syncthreads();
        if ((tid & 31) == 0) sred[tid >> 5] = v;
        __syncthreads();
        if (tid == 0) {
            float tsum = 0.f;
            #pragma unroll
            for (int i = 0; i < 8; i++) tsum += sred[i];
            res[k] = tsum;
        }
    }
    if (tid == 0) {
        float focal = res[1] > 0.f ? res[0] / res[1] : 0.f;
        float contr = res[3] > 0.f ? res[2] / res[3] : 0.f;
        out[0] = 0.6f * focal + 0.2f * contr;
    }
}

extern "C" void kernel_launch(void* const* d_in, const int* in_sizes, int n_in,
                              void* d_out, int out_size)
{
    const float* logits  = (const float*)d_in[0];
    const int*   targets = (const int*)d_in[1];
    const int*   mask    = (const int*)d_in[2];
    const float* emb     = (const float*)d_in[3];
    const int*   pids    = (const int*)d_in[4];
    const int*   amask   = (const int*)d_in[5];
    float* out = (float*)d_out;

    prep_kernel<<<NB, 256>>>(emb, pids, amask);
    contrast_kernel<<<NB * NNEG, 256>>>();
    focal_kernel<<<NROWS, 256>>>(logits, targets, mask);
    finalize_kernel<<<1, 256>>>(out);
}

// round 4
// speedup vs baseline: 2.0175x; 1.2198x over previous
#include <cuda_runtime.h>
#include <math_constants.h>
#include <stdint.h>

#define NROWS 8192      // B*M
#define VSZ   5003
#define NB    64
#define SSEQ  200
#define DDIM  128
#define NNEG  4
#define MAXA  8
#define INV_TAU (1.0f/0.07f)
#define NEGB  5          // negatives only ever come from batches 0..4
#define NRED  32         // partial-reduction blocks fused into contrast grid

// deterministic scratch (no atomics anywhere)
__device__ float g_fl[NROWS];
__device__ float g_cnt[NROWS];
__device__ float g_pfl[NRED];
__device__ float g_pcnt[NRED];
__device__ float g_nemb[NB * SSEQ * DDIM];       // normalized embeddings
__device__ unsigned char g_vld[NB * SSEQ];
__device__ int   g_aidx[NB][MAXA];
__device__ int   g_pidx[NB][MAXA];
__device__ int   g_na[NB];
__device__ float g_pm[NB][NNEG][MAXA];
__device__ float g_psum[NB][NNEG][MAXA];
__device__ float g_possim[NB][MAXA];

// ---------------- prep: normalize (only what's read later) + select -------
__global__ __launch_bounds__(256) void prep_kernel(
    const float* __restrict__ emb,
    const int*   __restrict__ pids,
    const int*   __restrict__ amask)
{
    int b = blockIdx.x;
    int tid = threadIdx.x, lane = tid & 31, w = tid >> 5;
    __shared__ unsigned char s_v[SSEQ];
    __shared__ int s_sel[16];
    if (tid < SSEQ) {
        unsigned char v = (amask[b * SSEQ + tid] == 1 && pids[b * SSEQ + tid] > 0) ? 1 : 0;
        s_v[tid] = v;
        g_vld[b * SSEQ + tid] = v;
    }
    __syncthreads();
    if (tid == 0) {
        int first16[16];
        #pragma unroll
        for (int i = 0; i < 16; i++) first16[i] = 0;
        int n = 0;
        for (int s = 0; s < SSEQ; s++) if (s_v[s]) { if (n < 16) first16[n] = s; n++; }
        int na = n / 2; if (na > MAXA) na = MAXA;
        g_na[b] = na;
        #pragma unroll
        for (int i = 0; i < MAXA; i++) {
            g_aidx[b][i] = first16[i];
            int pi = na + i;
            g_pidx[b][i] = (pi < 16) ? first16[pi] : 0;
            s_sel[i] = first16[i];
            s_sel[i + 8] = (pi < 16) ? first16[pi] : 0;
        }
    }
    __syncthreads();

    // normalize: batches 0..NEGB-1 need all 200 vectors (negative sources);
    // others only need their 16 selected anchor/positive vectors.
    if (b < NEGB) {
        for (int s = w; s < SSEQ; s += 8) {
            const float4* src = (const float4*)(emb + ((size_t)b * SSEQ + s) * DDIM);
            float4 x = src[lane];
            float n2 = x.x * x.x + x.y * x.y + x.z * x.z + x.w * x.w;
            #pragma unroll
            for (int o = 16; o; o >>= 1) n2 += __shfl_xor_sync(0xffffffffu, n2, o);
            float inv = 1.0f / fmaxf(sqrtf(n2), 1e-12f);
            x.x *= inv; x.y *= inv; x.z *= inv; x.w *= inv;
            ((float4*)(g_nemb + ((size_t)b * SSEQ + s) * DDIM))[lane] = x;
        }
    } else {
        #pragma unroll
        for (int q = 0; q < 2; q++) {
            int s = s_sel[w + 8 * q];   // duplicates write identical values: benign
            const float4* src = (const float4*)(emb + ((size_t)b * SSEQ + s) * DDIM);
            float4 x = src[lane];
            float n2 = x.x * x.x + x.y * x.y + x.z * x.z + x.w * x.w;
            #pragma unroll
            for (int o = 16; o; o >>= 1) n2 += __shfl_xor_sync(0xffffffffu, n2, o);
            float inv = 1.0f / fmaxf(sqrtf(n2), 1e-12f);
            x.x *= inv; x.y *= inv; x.z *= inv; x.w *= inv;
            ((float4*)(g_nemb + ((size_t)b * SSEQ + s) * DDIM))[lane] = x;
        }
    }
}

// ---------------- focal: one block per row, two-pass, loads kept in regs ---
__global__ __launch_bounds__(256) void focal_kernel(
    const float* __restrict__ logits,
    const int*   __restrict__ targets,
    const int*   __restrict__ mask)
{
    int r = blockIdx.x;
    int tid = threadIdx.x, lane = tid & 31, w = tid >> 5;
    int t = targets[r];
    bool valid = (t != -100) && (mask[r] == 1);
    if (!valid) {
        if (tid == 0) { g_fl[r] = 0.f; g_cnt[r] = 0.f; }
        return;
    }
    const float* row = logits + (size_t)r * VSZ;
    int pre = (4 - (int)(((uintptr_t)row >> 2) & 3)) & 3;   // peel to 16B align
    const float4* rv = (const float4*)(row + pre);
    int tail = pre + 5000;                                   // nvq == 1250 always

    float4 x0 = rv[tid];
    float4 x1 = rv[tid + 256];
    float4 x2 = rv[tid + 512];
    float4 x3 = rv[tid + 768];
    bool has4 = (tid < 226);
    float4 x4 = has4 ? rv[tid + 1024]
                     : make_float4(-CUDART_INF_F, -CUDART_INF_F, -CUDART_INF_F, -CUDART_INF_F);
    float e0 = -CUDART_INF_F, e1 = -CUDART_INF_F;
    if (tid < pre) e0 = row[tid];
    if (tail + tid < VSZ) e1 = row[tail + tid];

    float m0 = fmaxf(fmaxf(x0.x, x0.y), fmaxf(x0.z, x0.w));
    float m1 = fmaxf(fmaxf(x1.x, x1.y), fmaxf(x1.z, x1.w));
    float m2 = fmaxf(fmaxf(x2.x, x2.y), fmaxf(x2.z, x2.w));
    float m3 = fmaxf(fmaxf(x3.x, x3.y), fmaxf(x3.z, x3.w));
    float m4 = fmaxf(fmaxf(x4.x, x4.y), fmaxf(x4.z, x4.w));
    float m = fmaxf(fmaxf(fmaxf(m0, m1), fmaxf(m2, m3)), fmaxf(m4, fmaxf(e0, e1)));
    #pragma unroll
    for (int o = 16; o; o >>= 1) m = fmaxf(m, __shfl_xor_sync(0xffffffffu, m, o));
    __shared__ float sm[8], ss[8];
    if (lane == 0) sm[w] = m;
    __syncthreads();
    if (tid == 0) {
        float M = sm[0];
        #pragma unroll
        for (int i = 1; i < 8; i++) M = fmaxf(M, sm[i]);
        sm[0] = M;
    }
    __syncthreads();
    m = sm[0];

    float s0 = __expf(x0.x - m) + __expf(x0.y - m) + __expf(x0.z - m) + __expf(x0.w - m);
    float s1 = __expf(x1.x - m) + __expf(x1.y - m) + __expf(x1.z - m) + __expf(x1.w - m);
    float s2 = __expf(x2.x - m) + __expf(x2.y - m) + __expf(x2.z - m) + __expf(x2.w - m);
    float s3 = __expf(x3.x - m) + __expf(x3.y - m) + __expf(x3.z - m) + __expf(x3.w - m);
    float s4 = 0.f;
    if (has4) s4 = __expf(x4.x - m) + __expf(x4.y - m) + __expf(x4.z - m) + __expf(x4.w - m);
    float se = 0.f;
    if (e0 > -CUDART_INF_F) se += __expf(e0 - m);
    if (e1 > -CUDART_INF_F) se += __expf(e1 - m);
    float s = ((s0 + s1) + (s2 + s3)) + (s4 + se);
    #pragma unroll
    for (int o = 16; o; o >>= 1) s += __shfl_xor_sync(0xffffffffu, s, o);
    if (lane == 0) ss[w] = s;
    __syncthreads();
    if (tid == 0) {
        float S = 0.f;
        #pragma unroll
        for (int i = 0; i < 8; i++) S += ss[i];
        float lp = row[t] - m - logf(S);
        float pt = __expf(lp);
        float omp = 1.f - pt;
        g_fl[r]  = omp * omp * (-lp);
        g_cnt[r] = 1.f;
    }
}

// ---------------- contrastive (blocks 0..255) + g_fl partial reduce (256..287)
// Contrast: SMEM-tiled; warp = anchor, lane = negative; no shuffles in loop.
__global__ __launch_bounds__(256) void contrast_kernel()
{
    int blk = blockIdx.x;
    int tid = threadIdx.x, lane = tid & 31, w = tid >> 5;

    if (blk >= NB * NNEG) {
        // fused partial reduction of g_fl / g_cnt (focal ran before us)
        int k = blk - NB * NNEG;
        float f = g_fl[k * 256 + tid];
        float c = g_cnt[k * 256 + tid];
        #pragma unroll
        for (int o = 16; o; o >>= 1) {
            f += __shfl_xor_sync(0xffffffffu, f, o);
            c += __shfl_xor_sync(0xffffffffu, c, o);
        }
        __shared__ float sf[8], sc[8];
        if (lane == 0) { sf[w] = f; sc[w] = c; }
        __syncthreads();
        if (tid == 0) {
            float F = 0.f, C = 0.f;
            #pragma unroll
            for (int i = 0; i < 8; i++) { F += sf[i]; C += sc[i]; }
            g_pfl[k] = F; g_pcnt[k] = C;
        }
        return;
    }

    int b = blk >> 2, j = blk & 3;
    int nb = j + (j >= b ? 1 : 0);      // others[b][j]  (always < 5)

    __shared__ float s_anch[MAXA][DDIM];
    __shared__ float s_tile[32][132];   // 32 negs x 128 dims, padded (conflict-free)

    {   // warp w loads anchor w (unused anchors default to vector 0: normalized, safe)
        int ai = g_aidx[b][w];
        ((float4*)s_anch[w])[lane] =
            ((const float4*)(g_nemb + ((size_t)b * SSEQ + ai) * DDIM))[lane];
    }
    __syncthreads();
    int na = g_na[b];

    if (j == 0 && w < na) {
        int pi = g_pidx[b][w];
        float4 p  = ((const float4*)(g_nemb + ((size_t)b * SSEQ + pi) * DDIM))[lane];
        float4 a4 = ((const float4*)s_anch[w])[lane];
        float d = a4.x * p.x + a4.y * p.y + a4.z * p.z + a4.w * p.w;
        #pragma unroll
        for (int o = 16; o; o >>= 1) d += __shfl_xor_sync(0xffffffffu, d, o);
        if (lane == 0) g_possim[b][w] = d * INV_TAU;
    }

    const float* nbase = g_nemb + (size_t)nb * SSEQ * DDIM;
    const unsigned char* nvld = g_vld + nb * SSEQ;
    const float4* anch4 = (const float4*)s_anch[w];

    float m = -CUDART_INF_F, ssum = 0.f;
    for (int t = 0; t < 7; t++) {                 // ceil(200/32)
        int s0 = t * 32;
        int rem = SSEQ - s0; if (rem > 32) rem = 32;
        __syncthreads();                           // previous tile consumed
        for (int q = tid; q < rem * 32; q += 256) {
            int rowi = q >> 5, col = q & 31;
            *(float4*)&s_tile[rowi][col * 4] =
                ((const float4*)(nbase + (size_t)(s0 + rowi) * DDIM))[col];
        }
        __syncthreads();
        bool v = (lane < rem) && nvld[s0 + lane];
        float a0 = 0.f, a1 = 0.f, a2 = 0.f, a3 = 0.f;
        #pragma unroll
        for (int c = 0; c < 32; c += 4) {
            float4 n0 = *(const float4*)&s_tile[lane][(c + 0) * 4];
            float4 q0 = anch4[c + 0];
            float4 n1 = *(const float4*)&s_tile[lane][(c + 1) * 4];
            float4 q1 = anch4[c + 1];
            float4 n2 = *(const float4*)&s_tile[lane][(c + 2) * 4];
            float4 q2 = anch4[c + 2];
            float4 n3 = *(const float4*)&s_tile[lane][(c + 3) * 4];
            float4 q3 = anch4[c + 3];
            a0 += n0.x * q0.x + n0.y * q0.y + n0.z * q0.z + n0.w * q0.w;
            a1 += n1.x * q1.x + n1.y * q1.y + n1.z * q1.z + n1.w * q1.w;
            a2 += n2.x * q2.x + n2.y * q2.y + n2.z * q2.z + n2.w * q2.w;
            a3 += n3.x * q3.x + n3.y * q3.y + n3.z * q3.z + n3.w * q3.w;
        }
        if (v) {
            float sim = ((a0 + a1) + (a2 + a3)) * INV_TAU;
            float nm = fmaxf(m, sim);
            ssum = ssum * __expf(m - nm) + __expf(sim - nm);
            m = nm;
        }
    }
    // merge (m, ssum) across lanes (each lane covered a disjoint negative subset)
    #pragma unroll
    for (int o = 16; o; o >>= 1) {
        float om = __shfl_xor_sync(0xffffffffu, m, o);
        float os = __shfl_xor_sync(0xffffffffu, ssum, o);
        float nm = fmaxf(m, om);
        if (nm > -CUDART_INF_F) {
            ssum = ssum * __expf(m - nm) + os * __expf(om - nm);
            m = nm;
        }
    }
    if (lane == 0) { g_pm[b][j][w] = m; g_psum[b][j][w] = ssum; }
}

// ---------------- finalize: tiny now ---------------------------------------
__global__ __launch_bounds__(256) void finalize_kernel(float* __restrict__ out)
{
    int tid = threadIdx.x;
    __shared__ float sred[8];

    float fs  = (tid < NRED) ? g_pfl[tid]  : 0.f;
    float cnt = (tid < NRED) ? g_pcnt[tid] : 0.f;

    float closs = 0.f;
    for (int idx = tid; idx < NB * MAXA; idx += 256) {
        int b = idx >> 3, aq = idx & 7;
        if (aq < g_na[b]) {
            float ps = g_possim[b][aq];
            float m = ps, ssum = 1.f;
            #pragma unroll
            for (int jj = 0; jj < NNEG; jj++) {
                float pm  = g_pm[b][jj][aq];
                float pss = g_psum[b][jj][aq];
                if (pss > 0.f) {
                    float nm = fmaxf(m, pm);
                    ssum = ssum * __expf(m - nm) + pss * __expf(pm - nm);
                    m = nm;
                }
            }
            closs += (m + logf(ssum)) - ps;
        }
    }
    float pairs = (tid < NB) ? (float)g_na[tid] : 0.f;

    float vals[4] = { fs, cnt, closs, pairs };
    float res[4]  = { 0.f, 0.f, 0.f, 0.f };
    #pragma unroll
    for (int k = 0; k < 4; k++) {
        float v = vals[k];
        #pragma unroll
        for (int o = 16; o; o >>= 1) v += __shfl_xor_sync(0xffffffffu, v, o);
        __syncthreads();
        if ((tid & 31) == 0) sred[tid >> 5] = v;
        __syncthreads();
        if (tid == 0) {
            float tsum = 0.f;
            #pragma unroll
            for (int i = 0; i < 8; i++) tsum += sred[i];
            res[k] = tsum;
        }
    }
    if (tid == 0) {
        float focal = res[1] > 0.f ? res[0] / res[1] : 0.f;
        float contr = res[3] > 0.f ? res[2] / res[3] : 0.f;
        out[0] = 0.6f * focal + 0.2f * contr;
    }
}

extern "C" void kernel_launch(void* const* d_in, const int* in_sizes, int n_in,
                              void* d_out, int out_size)
{
    const float* logits  = (const float*)d_in[0];
    const int*   targets = (const int*)d_in[1];
    const int*   mask    = (const int*)d_in[2];
    const float* emb     = (const float*)d_in[3];
    const int*   pids    = (const int*)d_in[4];
    const int*   amask   = (const int*)d_in[5];
    float* out = (float*)d_out;

    prep_kernel<<<NB, 256>>>(emb, pids, amask);
    focal_kernel<<<NROWS, 256>>>(logits, targets, mask);
    contrast_kernel<<<NB * NNEG + NRED, 256>>>();
    finalize_kernel<<<1, 256>>>(out);
}